// round 1
// baseline (speedup 1.0000x reference)
#include <cuda_runtime.h>

#define NSER 8192
#define OBS 9
#define LOG2PI_F 1.8378770664093453f

static __device__ double g_partials[256];

__global__ void __launch_bounds__(32) kf_kernel(
    const float* __restrict__ y,
    const float* __restrict__ B1s1_p,
    const float* __restrict__ B1s2_p,
    const float* __restrict__ lam1_p,
    const float* __restrict__ lam2_p,
    const float* __restrict__ logq_p,
    const float* __restrict__ logr_p,
    const float* __restrict__ gami_p,
    const float* __restrict__ gamc_p,
    int NT)
{
    const int n = blockIdx.x * 32 + threadIdx.x;

    // ---------------- constants (tiny inputs, L2/L1 broadcast) ----------------
    float B[3][3];
#pragma unroll
    for (int i = 0; i < 3; ++i)
#pragma unroll
        for (int j = 0; j < 3; ++j)
            B[i][j] = B1s1_p[i * 3 + j];
    const float b3 = B1s2_p[0];

    float q[4];
#pragma unroll
    for (int l = 0; l < 4; ++l) q[l] = expf(logq_p[l]);

    float c1[9], c2[9], dinv[9];
    c1[0] = 1.f; c1[1] = lam1_p[0]; c1[2] = lam1_p[1];
    c1[3] = 1.f; c1[4] = lam1_p[2]; c1[5] = lam1_p[3];
    c1[6] = 1.f; c1[7] = lam1_p[4]; c1[8] = lam1_p[5];
    c2[0] = 1.f;
#pragma unroll
    for (int o = 1; o < 9; ++o) c2[o] = lam2_p[o - 1];

    float logdetD = 0.f;
    float a1[3] = {0.f, 0.f, 0.f};
    float b1[3] = {0.f, 0.f, 0.f};
    float a2 = 0.f, b2 = 0.f;
#pragma unroll
    for (int o = 0; o < 9; ++o) {
        float r = expf(logr_p[o]);
        float d = r + 1e-6f;          // jitter, matches reference F = ... + R + 1e-6 I
        float di = 1.f / d;
        dinv[o] = di;
        logdetD += logf(d);
        float cd = c1[o] * di;
        a1[o / 3] += c1[o] * cd;      // U^T D^-1 U (diagonal, disjoint support)
        b1[o / 3] += cd * cd * r;     // for K R K^T (R WITHOUT jitter, per reference)
        float e = c2[o] * di;
        a2 += c2[o] * e;
        b2 += e * e * r;
    }
    const float g0 = gami_p[0];
    const float gc0 = gamc_p[0], gc1 = gamc_p[1], gc2 = gamc_p[2];

    // ---------------- state ----------------
    float P[4][4];
#pragma unroll
    for (int i = 0; i < 4; ++i)
#pragma unroll
        for (int j = 0; j < 4; ++j)
            P[i][j] = (i == j) ? 1000.f : 0.f;
    float eta[4] = {0.f, 0.f, 0.f, 0.f};
    float p1 = 0.99f, p2 = 0.01f;
    double ll = 0.0;

    const float* yp = y + (long long)n * NT * OBS;
    float yc[9];
#pragma unroll
    for (int o = 0; o < 9; ++o) yc[o] = yp[o];

#pragma unroll 1
    for (int t = 0; t < NT; ++t) {
        // ---- prefetch next step's observations (overlaps DRAM latency) ----
        float yn[9];
        {
            const float* ynp = yp + (t + 1) * OBS;
            const bool have = (t + 1) < NT;
#pragma unroll
            for (int o = 0; o < 9; ++o) yn[o] = have ? ynp[o] : 0.f;
        }

        // ---- regime transition prob (uses PRE-update eta) ----
        float lg = g0 + gc0 * eta[0] + gc1 * eta[1] + gc2 * eta[2];
        float p11 = __fdividef(1.f, 1.f + __expf(-lg));
        float p12 = 1.f - p11;

        // ---- predict: eta_pred = B eta (block-diag), P_pred = B P B^T + Q ----
        float ep[4];
        ep[0] = B[0][0] * eta[0] + B[0][1] * eta[1] + B[0][2] * eta[2];
        ep[1] = B[1][0] * eta[0] + B[1][1] * eta[1] + B[1][2] * eta[2];
        ep[2] = B[2][0] * eta[0] + B[2][1] * eta[1] + B[2][2] * eta[2];
        ep[3] = b3 * eta[3];

        float T[4][4];
#pragma unroll
        for (int i = 0; i < 3; ++i)
#pragma unroll
            for (int j = 0; j < 4; ++j)
                T[i][j] = B[i][0] * P[0][j] + B[i][1] * P[1][j] + B[i][2] * P[2][j];
#pragma unroll
        for (int j = 0; j < 4; ++j) T[3][j] = b3 * P[3][j];

        float Pp[4][4];
#pragma unroll
        for (int i = 0; i < 4; ++i) {
#pragma unroll
            for (int j = 0; j < 3; ++j)
                Pp[i][j] = T[i][0] * B[j][0] + T[i][1] * B[j][1] + T[i][2] * B[j][2];
            Pp[i][3] = T[i][3] * b3;
        }
        Pp[0][0] += q[0]; Pp[1][1] += q[1]; Pp[2][2] += q[2]; Pp[3][3] += q[3];

        // ================= Regime 1: F1 = U M U^T + D (rank-3 Woodbury) =================
        float m00 = Pp[0][0], m01 = Pp[0][1], m02 = Pp[0][2];
        float m11 = Pp[1][1], m12 = Pp[1][2], m22 = Pp[2][2];
        // adjugate inverse of symmetric 3x3 M
        float A00 = m11 * m22 - m12 * m12;
        float A01 = m02 * m12 - m01 * m22;
        float A02 = m01 * m12 - m02 * m11;
        float A11 = m00 * m22 - m02 * m02;
        float A12 = m01 * m02 - m00 * m12;
        float A22 = m00 * m11 - m01 * m01;
        float detM = m00 * A00 + m01 * A01 + m02 * A02;
        float idM = __fdividef(1.f, detM);
        float Mi00 = A00 * idM, Mi01 = A01 * idM, Mi02 = A02 * idM;
        float Mi11 = A11 * idM, Mi12 = A12 * idM, Mi22 = A22 * idM;
        // N = M^-1 + diag(a1); W = N^-1
        float n00 = Mi00 + a1[0], n01 = Mi01, n02 = Mi02;
        float n11 = Mi11 + a1[1], n12 = Mi12, n22 = Mi22 + a1[2];
        float C00 = n11 * n22 - n12 * n12;
        float C01 = n02 * n12 - n01 * n22;
        float C02 = n01 * n12 - n02 * n11;
        float C11 = n00 * n22 - n02 * n02;
        float C12 = n01 * n02 - n00 * n12;
        float C22 = n00 * n11 - n01 * n01;
        float detN = n00 * C00 + n01 * C01 + n02 * C02;
        float idN = __fdividef(1.f, detN);
        float W00 = C00 * idN, W01 = C01 * idN, W02 = C02 * idN;
        float W11 = C11 * idN, W12 = C12 * idN, W22 = C22 * idN;
        // logdet F1 = logdet D + log(detM * detN)   (matrix determinant lemma)
        float hld1 = logdetD + __logf(detM * detN);

        // innovation, u = U^T D^-1 v, quadD = v^T D^-1 v
        float u0 = 0.f, u1 = 0.f, u2v = 0.f, quadD = 0.f;
#pragma unroll
        for (int o = 0; o < 9; ++o) {
            float v = yc[o] - c1[o] * ep[o / 3];
            float sv = v * dinv[o];
            quadD += v * sv;
            float csv = c1[o] * sv;
            if (o < 3) u0 += csv; else if (o < 6) u1 += csv; else u2v += csv;
        }
        float quad1 = quadD - (u0 * (W00 * u0 + W01 * u1 + W02 * u2v)
                             + u1 * (W01 * u0 + W11 * u1 + W12 * u2v)
                             + u2v * (W02 * u0 + W12 * u1 + W22 * u2v));
        float lp1 = -0.5f * (quad1 + 9.f * LOG2PI_F) - 0.5f * hld1;

        // G = I - diag(a1) W ;  K1s = Pp[:,0:3] G  (compressed Kalman gain)
        float G00 = 1.f - a1[0] * W00, G01 = -a1[0] * W01, G02 = -a1[0] * W02;
        float G10 = -a1[1] * W01, G11 = 1.f - a1[1] * W11, G12 = -a1[1] * W12;
        float G20 = -a1[2] * W02, G21 = -a1[2] * W12, G22 = 1.f - a1[2] * W22;

        float K1s[4][3], Ka[4][3];
#pragma unroll
        for (int l = 0; l < 4; ++l) {
            K1s[l][0] = Pp[l][0] * G00 + Pp[l][1] * G10 + Pp[l][2] * G20;
            K1s[l][1] = Pp[l][0] * G01 + Pp[l][1] * G11 + Pp[l][2] * G21;
            K1s[l][2] = Pp[l][0] * G02 + Pp[l][1] * G12 + Pp[l][2] * G22;
            Ka[l][0] = K1s[l][0] * a1[0];
            Ka[l][1] = K1s[l][1] * a1[1];
            Ka[l][2] = K1s[l][2] * a1[2];
        }
        float eta1[4];
#pragma unroll
        for (int l = 0; l < 4; ++l)
            eta1[l] = ep[l] + K1s[l][0] * u0 + K1s[l][1] * u1 + K1s[l][2] * u2v;

        // Joseph form: P1 = (I-K1 L1) Pp (I-K1 L1)^T + K1 R K1^T
        float T1[4][4];
#pragma unroll
        for (int l = 0; l < 4; ++l)
#pragma unroll
            for (int j = 0; j < 4; ++j)
                T1[l][j] = Pp[l][j] - Ka[l][0] * Pp[0][j] - Ka[l][1] * Pp[1][j] - Ka[l][2] * Pp[2][j];
        float P1[4][4];
#pragma unroll
        for (int l = 0; l < 4; ++l)
#pragma unroll
            for (int j = l; j < 4; ++j) {
                float vv = T1[l][j] - T1[l][0] * Ka[j][0] - T1[l][1] * Ka[j][1] - T1[l][2] * Ka[j][2]
                         + b1[0] * K1s[l][0] * K1s[j][0]
                         + b1[1] * K1s[l][1] * K1s[j][1]
                         + b1[2] * K1s[l][2] * K1s[j][2];
                P1[l][j] = vv; P1[j][l] = vv;
            }

        // ================= Regime 2: F2 = s c c^T + D (rank-1 Sherman-Morrison) =================
        float s = Pp[3][3];
        float denom = 1.f + s * a2;
        float iden = __fdividef(1.f, denom);
        float k2[4];
#pragma unroll
        for (int l = 0; l < 4; ++l) k2[l] = Pp[l][3] * iden;

        float u2s = 0.f, quadD2 = 0.f;
#pragma unroll
        for (int o = 0; o < 9; ++o) {
            float v = yc[o] - c2[o] * ep[3];
            float sv = v * dinv[o];
            quadD2 += v * sv;
            u2s += c2[o] * sv;
        }
        float quad2 = quadD2 - s * u2s * u2s * iden;
        float lp2 = -0.5f * (quad2 + 9.f * LOG2PI_F) - 0.5f * (logdetD + __logf(denom));

        float eta2[4];
#pragma unroll
        for (int l = 0; l < 4; ++l) eta2[l] = ep[l] + k2[l] * u2s;

        float T2[4][4];
#pragma unroll
        for (int l = 0; l < 4; ++l)
#pragma unroll
            for (int j = 0; j < 4; ++j)
                T2[l][j] = Pp[l][j] - a2 * k2[l] * Pp[3][j];
        float P2[4][4];
#pragma unroll
        for (int l = 0; l < 4; ++l)
#pragma unroll
            for (int j = l; j < 4; ++j) {
                float vv = T2[l][j] - a2 * T2[l][3] * k2[j] + b2 * k2[l] * k2[j];
                P2[l][j] = vv; P2[j][l] = vv;
            }

        // ================= mixture collapse =================
        float lik1 = __expf(lp1);
        float lik2 = __expf(lp2);
        float num1 = lik1 * (p1 * p11);            // p21 = 0
        float num2 = lik2 * (p1 * p12 + p2);       // p22 = 1
        float marg = num1 + num2 + 1e-9f;
        float im = __fdividef(1.f, marg);
        float pt1 = num1 * im, pt2 = num2 * im;
        ll += (double)__logf(marg);

        float etn[4], dd1[4], dd2[4];
#pragma unroll
        for (int l = 0; l < 4; ++l) {
            etn[l] = pt1 * eta1[l] + pt2 * eta2[l];
            dd1[l] = eta1[l] - etn[l];
            dd2[l] = eta2[l] - etn[l];
        }
#pragma unroll
        for (int l = 0; l < 4; ++l) {
            eta[l] = etn[l];
#pragma unroll
            for (int j = l; j < 4; ++j) {
                float pn = pt1 * (P1[l][j] + dd1[l] * dd1[j])
                         + pt2 * (P2[l][j] + dd2[l] * dd2[j]);
                P[l][j] = pn; P[j][l] = pn;
            }
        }
        p1 = pt1; p2 = pt2;
#pragma unroll
        for (int o = 0; o < 9; ++o) yc[o] = yn[o];
    }

    // ---- deterministic warp reduction -> per-block partial ----
    double v = ll;
#pragma unroll
    for (int off = 16; off > 0; off >>= 1)
        v += __shfl_down_sync(0xffffffffu, v, off);
    if (threadIdx.x == 0) g_partials[blockIdx.x] = v;
}

__global__ void reduce_kernel(float* out)
{
    __shared__ double sh[256];
    const int t = threadIdx.x;
    sh[t] = g_partials[t];
    __syncthreads();
    for (int k = 128; k > 0; k >>= 1) {
        if (t < k) sh[t] += sh[t + k];
        __syncthreads();
    }
    if (t == 0) out[0] = (float)(-sh[0]);
}

extern "C" void kernel_launch(void* const* d_in, const int* in_sizes, int n_in,
                              void* d_out, int out_size)
{
    const float* y    = (const float*)d_in[0];
    const float* B1s1 = (const float*)d_in[1];
    const float* B1s2 = (const float*)d_in[2];
    const float* lam1 = (const float*)d_in[3];
    const float* lam2 = (const float*)d_in[4];
    const float* logq = (const float*)d_in[5];
    const float* logr = (const float*)d_in[6];
    const float* gami = (const float*)d_in[7];
    const float* gamc = (const float*)d_in[8];

    const int NT = in_sizes[0] / (NSER * OBS);   // 400

    kf_kernel<<<NSER / 32, 32>>>(y, B1s1, B1s2, lam1, lam2, logq, logr, gami, gamc, NT);
    reduce_kernel<<<1, 256>>>((float*)d_out);
}

// round 2
// speedup vs baseline: 1.0140x; 1.0140x over previous
#include <cuda_runtime.h>

#define NSER 8192
#define OBS 9
#define LOG2PI_F 1.8378770664093453f

static __device__ double g_partials[256];

// Block = 64 threads = 2 warps = one "pair" handling 32 series.
// Warp A (threads 0-31): regime-1 (heavy).  Warp B (threads 32-63): regime-2 (light).
// Exchange of per-regime results via double-buffered smem, 1 barrier/step.
__global__ void __launch_bounds__(64) kf_kernel(
    const float* __restrict__ y,
    const float* __restrict__ B1s1_p,
    const float* __restrict__ B1s2_p,
    const float* __restrict__ lam1_p,
    const float* __restrict__ lam2_p,
    const float* __restrict__ logq_p,
    const float* __restrict__ logr_p,
    const float* __restrict__ gami_p,
    const float* __restrict__ gamc_p,
    int NT)
{
    const int lane = threadIdx.x & 31;
    const bool isA = threadIdx.x < 32;
    const int n = blockIdx.x * 32 + lane;

    // [parity][who: 0=A's msg, 1=B's msg][lane][slot(15, padded 17)]
    __shared__ float xch[2][2][32][17];

    // ---------------- constants ----------------
    float B[3][3];
#pragma unroll
    for (int i = 0; i < 3; ++i)
#pragma unroll
        for (int j = 0; j < 3; ++j)
            B[i][j] = B1s1_p[i * 3 + j];
    const float b3 = B1s2_p[0];

    float q[4];
#pragma unroll
    for (int l = 0; l < 4; ++l) q[l] = expf(logq_p[l]);

    float c1[9], c2[9], dinv[9];
    c1[0] = 1.f; c1[1] = lam1_p[0]; c1[2] = lam1_p[1];
    c1[3] = 1.f; c1[4] = lam1_p[2]; c1[5] = lam1_p[3];
    c1[6] = 1.f; c1[7] = lam1_p[4]; c1[8] = lam1_p[5];
    c2[0] = 1.f;
#pragma unroll
    for (int o = 1; o < 9; ++o) c2[o] = lam2_p[o - 1];

    float logdetD = 0.f;
    float a1[3] = {0.f, 0.f, 0.f};
    float a2 = 0.f;
#pragma unroll
    for (int o = 0; o < 9; ++o) {
        float r = expf(logr_p[o]);
        float d = r + 1e-6f;
        float di = 1.f / d;
        dinv[o] = di;
        logdetD += logf(d);
        a1[o / 3] += c1[o] * c1[o] * di;  // U^T D^-1 U (diag, disjoint support)
        a2 += c2[o] * c2[o] * di;
    }
    const float g0 = gami_p[0];
    const float gc0 = gamc_p[0], gc1 = gamc_p[1], gc2 = gamc_p[2];

    // ---------------- state (replicated in both warps) ----------------
    float P[4][4];
#pragma unroll
    for (int i = 0; i < 4; ++i)
#pragma unroll
        for (int j = 0; j < 4; ++j)
            P[i][j] = (i == j) ? 1000.f : 0.f;
    float eta[4] = {0.f, 0.f, 0.f, 0.f};
    float p1 = 0.99f, p2 = 0.01f;
    double ll = 0.0;

    const float* yp = y + (size_t)n * NT * OBS;
    float yc[9];
#pragma unroll
    for (int o = 0; o < 9; ++o) yc[o] = yp[o];

#pragma unroll 1
    for (int t = 0; t < NT; ++t) {
        // ---- prefetch next step's observations ----
        float yn[9];
        {
            const float* ynp = yp + (t + 1) * OBS;
            const bool have = (t + 1) < NT;
#pragma unroll
            for (int o = 0; o < 9; ++o) yn[o] = have ? ynp[o] : 0.f;
        }

        // ---- transition prob (pre-update eta) ----
        float lg = g0 + gc0 * eta[0] + gc1 * eta[1] + gc2 * eta[2];
        float p11 = __fdividef(1.f, 1.f + __expf(-lg));
        float p12 = 1.f - p11;

        // ---- predict (duplicated in both warps) ----
        float ep[4];
        ep[0] = B[0][0] * eta[0] + B[0][1] * eta[1] + B[0][2] * eta[2];
        ep[1] = B[1][0] * eta[0] + B[1][1] * eta[1] + B[1][2] * eta[2];
        ep[2] = B[2][0] * eta[0] + B[2][1] * eta[1] + B[2][2] * eta[2];
        ep[3] = b3 * eta[3];

        float T[4][4];
#pragma unroll
        for (int i = 0; i < 3; ++i)
#pragma unroll
            for (int j = 0; j < 4; ++j)
                T[i][j] = B[i][0] * P[0][j] + B[i][1] * P[1][j] + B[i][2] * P[2][j];
#pragma unroll
        for (int j = 0; j < 4; ++j) T[3][j] = b3 * P[3][j];

        float Pp[4][4];
#pragma unroll
        for (int i = 0; i < 4; ++i) {
#pragma unroll
            for (int j = 0; j < 3; ++j)
                Pp[i][j] = T[i][0] * B[j][0] + T[i][1] * B[j][1] + T[i][2] * B[j][2];
            Pp[i][3] = T[i][3] * b3;
        }
        Pp[0][0] += q[0]; Pp[1][1] += q[1]; Pp[2][2] += q[2]; Pp[3][3] += q[3];

        float msg[15];
        if (isA) {
            // ===== Regime 1: F1 = U M U^T + D, rank-3 Woodbury =====
            float m00 = Pp[0][0], m01 = Pp[0][1], m02 = Pp[0][2];
            float m11 = Pp[1][1], m12 = Pp[1][2], m22 = Pp[2][2];
            float A00 = m11 * m22 - m12 * m12;
            float A01 = m02 * m12 - m01 * m22;
            float A02 = m01 * m12 - m02 * m11;
            float A11 = m00 * m22 - m02 * m02;
            float A12 = m01 * m02 - m00 * m12;
            float A22 = m00 * m11 - m01 * m01;
            float detM = m00 * A00 + m01 * A01 + m02 * A02;
            float idM = __fdividef(1.f, detM);
            float n00 = A00 * idM + a1[0], n01 = A01 * idM, n02 = A02 * idM;
            float n11 = A11 * idM + a1[1], n12 = A12 * idM;
            float n22 = A22 * idM + a1[2];
            float C00 = n11 * n22 - n12 * n12;
            float C01 = n02 * n12 - n01 * n22;
            float C02 = n01 * n12 - n02 * n11;
            float C11 = n00 * n22 - n02 * n02;
            float C12 = n01 * n02 - n00 * n12;
            float C22 = n00 * n11 - n01 * n01;
            float detN = n00 * C00 + n01 * C01 + n02 * C02;
            float idN = __fdividef(1.f, detN);
            float W00 = C00 * idN, W01 = C01 * idN, W02 = C02 * idN;
            float W11 = C11 * idN, W12 = C12 * idN, W22 = C22 * idN;
            float hld1 = logdetD + __logf(detM * detN);

            float u0 = 0.f, u1 = 0.f, u2v = 0.f, quadD = 0.f;
#pragma unroll
            for (int o = 0; o < 9; ++o) {
                float v = yc[o] - c1[o] * ep[o / 3];
                float sv = v * dinv[o];
                quadD += v * sv;
                float csv = c1[o] * sv;
                if (o < 3) u0 += csv; else if (o < 6) u1 += csv; else u2v += csv;
            }
            float quad1 = quadD - (u0 * (W00 * u0 + W01 * u1 + W02 * u2v)
                                 + u1 * (W01 * u0 + W11 * u1 + W12 * u2v)
                                 + u2v * (W02 * u0 + W12 * u1 + W22 * u2v));
            float lp1 = -0.5f * (quad1 + 9.f * LOG2PI_F) - 0.5f * hld1;

            float G00 = 1.f - a1[0] * W00, G01 = -a1[0] * W01, G02 = -a1[0] * W02;
            float G10 = -a1[1] * W01, G11 = 1.f - a1[1] * W11, G12 = -a1[1] * W12;
            float G20 = -a1[2] * W02, G21 = -a1[2] * W12, G22 = 1.f - a1[2] * W22;

            float K1s[4][3], Ka[4][3];
#pragma unroll
            for (int l = 0; l < 4; ++l) {
                K1s[l][0] = Pp[l][0] * G00 + Pp[l][1] * G10 + Pp[l][2] * G20;
                K1s[l][1] = Pp[l][0] * G01 + Pp[l][1] * G11 + Pp[l][2] * G21;
                K1s[l][2] = Pp[l][0] * G02 + Pp[l][1] * G12 + Pp[l][2] * G22;
                Ka[l][0] = K1s[l][0] * a1[0];
                Ka[l][1] = K1s[l][1] * a1[1];
                Ka[l][2] = K1s[l][2] * a1[2];
            }
#pragma unroll
            for (int l = 0; l < 4; ++l)
                msg[l] = ep[l] + K1s[l][0] * u0 + K1s[l][1] * u1 + K1s[l][2] * u2v;

            // short-form P1 = (I - K1 L1) Pp  (upper triangle; Joseph-form delta
            // is exactly 1e-6 * K K^T from the jitter -> negligible)
            int idx = 4;
#pragma unroll
            for (int l = 0; l < 4; ++l)
#pragma unroll
                for (int j = 0; j < 4; ++j)
                    if (j >= l) {
                        msg[idx++] = Pp[l][j] - Ka[l][0] * Pp[0][j]
                                              - Ka[l][1] * Pp[1][j]
                                              - Ka[l][2] * Pp[2][j];
                    }
            msg[14] = lp1;
        } else {
            // ===== Regime 2: F2 = s c c^T + D, rank-1 Sherman-Morrison =====
            float s = Pp[3][3];
            float denom = 1.f + s * a2;
            float iden = __fdividef(1.f, denom);
            float k2[4], ak[4];
#pragma unroll
            for (int l = 0; l < 4; ++l) { k2[l] = Pp[l][3] * iden; ak[l] = a2 * k2[l]; }

            float u2s = 0.f, quadD2 = 0.f;
#pragma unroll
            for (int o = 0; o < 9; ++o) {
                float v = yc[o] - c2[o] * ep[3];
                float sv = v * dinv[o];
                quadD2 += v * sv;
                u2s += c2[o] * sv;
            }
            float quad2 = quadD2 - s * u2s * u2s * iden;
            float lp2 = -0.5f * (quad2 + 9.f * LOG2PI_F)
                      - 0.5f * (logdetD + __logf(denom));

#pragma unroll
            for (int l = 0; l < 4; ++l) msg[l] = ep[l] + k2[l] * u2s;

            int idx = 4;
#pragma unroll
            for (int l = 0; l < 4; ++l)
#pragma unroll
                for (int j = 0; j < 4; ++j)
                    if (j >= l)
                        msg[idx++] = Pp[l][j] - ak[l] * Pp[3][j];
            msg[14] = lp2;
        }

        // ---- exchange (double-buffered, single barrier) ----
        float* myb = &xch[t & 1][isA ? 0 : 1][lane][0];
#pragma unroll
        for (int s = 0; s < 15; ++s) myb[s] = msg[s];
        __syncthreads();
        const float* ob = &xch[t & 1][isA ? 1 : 0][lane][0];
        float oth[15];
#pragma unroll
        for (int s = 0; s < 15; ++s) oth[s] = ob[s];

        const float* m1 = isA ? msg : oth;   // regime-1 results
        const float* m2 = isA ? oth : msg;   // regime-2 results

        // ---- mixture collapse (duplicated in both warps) ----
        float lik1 = __expf(m1[14]);
        float lik2 = __expf(m2[14]);
        float num1 = lik1 * (p1 * p11);           // p21 = 0
        float num2 = lik2 * (p1 * p12 + p2);      // p22 = 1
        float marg = num1 + num2 + 1e-9f;
        float im = __fdividef(1.f, marg);
        float pt1 = num1 * im, pt2 = num2 * im;
        if (isA) ll += (double)__logf(marg);

        float dd1[4], dd2[4];
#pragma unroll
        for (int l = 0; l < 4; ++l) {
            float e = pt1 * m1[l] + pt2 * m2[l];
            dd1[l] = m1[l] - e;
            dd2[l] = m2[l] - e;
            eta[l] = e;
        }
        {
            int idx = 4;
#pragma unroll
            for (int l = 0; l < 4; ++l)
#pragma unroll
                for (int j = 0; j < 4; ++j)
                    if (j >= l) {
                        float pn = pt1 * (m1[idx] + dd1[l] * dd1[j])
                                 + pt2 * (m2[idx] + dd2[l] * dd2[j]);
                        P[l][j] = pn; P[j][l] = pn;
                        ++idx;
                    }
        }
        p1 = pt1; p2 = pt2;
#pragma unroll
        for (int o = 0; o < 9; ++o) yc[o] = yn[o];
    }

    // ---- deterministic reduction: warp A only carries ll ----
    if (isA) {
        double v = ll;
#pragma unroll
        for (int off = 16; off > 0; off >>= 1)
            v += __shfl_down_sync(0xffffffffu, v, off);
        if (lane == 0) g_partials[blockIdx.x] = v;
    }
}

__global__ void reduce_kernel(float* out)
{
    __shared__ double sh[256];
    const int t = threadIdx.x;
    sh[t] = g_partials[t];
    __syncthreads();
    for (int k = 128; k > 0; k >>= 1) {
        if (t < k) sh[t] += sh[t + k];
        __syncthreads();
    }
    if (t == 0) out[0] = (float)(-sh[0]);
}

extern "C" void kernel_launch(void* const* d_in, const int* in_sizes, int n_in,
                              void* d_out, int out_size)
{
    const float* y    = (const float*)d_in[0];
    const float* B1s1 = (const float*)d_in[1];
    const float* B1s2 = (const float*)d_in[2];
    const float* lam1 = (const float*)d_in[3];
    const float* lam2 = (const float*)d_in[4];
    const float* logq = (const float*)d_in[5];
    const float* logr = (const float*)d_in[6];
    const float* gami = (const float*)d_in[7];
    const float* gamc = (const float*)d_in[8];

    const int NT = in_sizes[0] / (NSER * OBS);   // 400

    kf_kernel<<<NSER / 32, 64>>>(y, B1s1, B1s2, lam1, lam2, logq, logr, gami, gamc, NT);
    reduce_kernel<<<1, 256>>>((float*)d_out);
}